// round 5
// baseline (speedup 1.0000x reference)
#include <cuda_runtime.h>
#include <math.h>
#include <stdint.h>

typedef unsigned long long ull;

// ---------------- problem constants ----------------
#define kNQ 10000
#define kNS 500
#define kQN 4
#define kSN 10
#define kB  32
#define kS  200
#define kD  128
#define kT  199   // S-1

// ---------------- scratch layout (floats) ----------------
__host__ __device__ constexpr size_t O_TA0 = 0;
__host__ __device__ constexpr size_t O_TA1 = O_TA0 + (size_t)kNQ*kD;
__host__ __device__ constexpr size_t O_TA2 = O_TA1 + (size_t)kNS*kD;
__host__ __device__ constexpr size_t O_TB0 = O_TA2 + (size_t)kNQ*kD;
__host__ __device__ constexpr size_t O_TB1 = O_TB0 + (size_t)kNQ*kD;
__host__ __device__ constexpr size_t O_A   = O_TB1 + (size_t)kNS*kD;
__host__ __device__ constexpr size_t O_H   = O_A   + (size_t)kNQ*kD;
__host__ __device__ constexpr size_t O_AS  = O_H   + (size_t)kB*kS*kD;
__host__ __device__ constexpr size_t O_V   = O_AS  + (size_t)kB*kT;   // qv[128], kv[128], c_q, c_k
__host__ __device__ constexpr size_t O_RG  = O_V   + 258;             // r_gates 2x512
__host__ __device__ constexpr size_t G_TOTAL = O_RG + 1024;

__device__ float g_buf[G_TOTAL];

// ---------------- fast math ----------------
__device__ __forceinline__ float fast_tanh(float x) {
    float y;
    asm("tanh.approx.f32 %0, %1;" : "=f"(y) : "f"(x));
    return y;
}
__device__ __forceinline__ float fast_sigmoid(float x) {
    return 0.5f * fast_tanh(0.5f * x) + 0.5f;
}
// packed f32x2 FMA (FFMA2)
__device__ __forceinline__ ull fma2(ull a, ull b, ull c) {
    ull d;
    asm("fma.rn.f32x2 %0, %1, %2, %3;" : "=l"(d) : "l"(a), "l"(b), "l"(c));
    return d;
}
__device__ __forceinline__ ull pack2(float x) {
    ull d; asm("mov.b64 %0, {%1, %1};" : "=l"(d) : "f"(x)); return d;
}
__device__ __forceinline__ float2 unpack2(ull v) {
    float2 r; asm("mov.b64 {%0, %1}, %2;" : "=f"(r.x), "=f"(r.y) : "l"(v)); return r;
}

// ---------------- task structs ----------------
struct HopTask {
    const float* base;
    const int*   nbrs;
    const float* tbl;
    const float* W;
    const float* bias;
    float*       out;
    int knbr; float invk;
    int R; int blk0;
};
struct PrepArgs {
    const float *qW, *qb, *kW, *kb, *wW, *embr, *Wih, *bih, *bhh;
    int enable;
};
struct HopParams { HopTask t[3]; int nt; PrepArgs prep; };

// ---------------- fused multi-task hop kernel (256 thr, 64 rows, 4x8 packed) ----------------
__global__ __launch_bounds__(256, 2) void hop_kernel(const HopParams p)
{
    extern __shared__ float sm[];
    float* sW  = sm;                 // 128x128
    float* sIn = sm + kD*kD;         // 64x132
    const int tid = threadIdx.x;

    // prep block (independent side-work; consumers run 3 kernels later)
    if (p.prep.enable && blockIdx.x == (int)gridDim.x - 1) {
        const PrepArgs& A = p.prep;
        float* vec = g_buf + O_V;
        float* rg  = g_buf + O_RG;
        if (tid < kD) {
            float sq = 0.f, sk = 0.f;
            #pragma unroll 4
            for (int j = 0; j < kD; j++) {
                sq += A.qW[tid*kD + j] * A.wW[j];
                sk += A.kW[tid*kD + j] * A.wW[kD + j];
            }
            vec[tid]      = sq;
            vec[kD + tid] = sk;
        }
        if (tid == 128) {
            float s = 0.f;
            for (int j = 0; j < kD; j++) s += A.qb[j] * A.wW[j];
            vec[256] = s;
        }
        if (tid == 129) {
            float s = 0.f;
            for (int j = 0; j < kD; j++) s += A.kb[j] * A.wW[kD + j];
            vec[257] = s;
        }
        for (int c = tid; c < 512; c += 256) {
            for (int r = 0; r < 2; r++) {
                float s = A.bih[c] + A.bhh[c];
                #pragma unroll 4
                for (int k = 0; k < kD; k++)
                    s += A.embr[r*kD + k] * A.Wih[(size_t)(kD + k)*512 + c];
                rg[r*512 + c] = s;
            }
        }
        return;
    }

    int ti = 0;
    #pragma unroll
    for (int i = 1; i < 3; i++)
        if (i < p.nt && (int)blockIdx.x >= p.t[i].blk0) ti = i;
    const HopTask& T = p.t[ti];
    const int row0 = (blockIdx.x - T.blk0) * 64;

    // load W (128x128): 4096 float4 / 256 thr
    {
        const float4* Wp = (const float4*)T.W;
        #pragma unroll
        for (int i = 0; i < 16; i++)
            ((float4*)sW)[tid + i*256] = __ldg(&Wp[tid + i*256]);
    }

    // gather 64 input rows (4 threads/row, 32 dims = 8 float4 each)
    {
        int lr = tid >> 2, part = tid & 3;
        int gr = row0 + lr;
        float4 v[8];
        if (gr < T.R) {
            const float4* bp = (const float4*)(T.base + (size_t)gr*kD) + part*8;
            #pragma unroll
            for (int d = 0; d < 8; d++) v[d] = __ldg(&bp[d]);
            if (T.knbr > 0) {
                float4 s[8];
                #pragma unroll
                for (int d = 0; d < 8; d++) s[d] = make_float4(0.f,0.f,0.f,0.f);
                for (int j = 0; j < T.knbr; j++) {
                    int nb = __ldg(&T.nbrs[(size_t)gr*T.knbr + j]);
                    const float4* tp = (const float4*)(T.tbl + (size_t)nb*kD) + part*8;
                    #pragma unroll
                    for (int d = 0; d < 8; d++) {
                        float4 x = __ldg(&tp[d]);
                        s[d].x += x.x; s[d].y += x.y; s[d].z += x.z; s[d].w += x.w;
                    }
                }
                #pragma unroll
                for (int d = 0; d < 8; d++) {
                    v[d].x += s[d].x * T.invk; v[d].y += s[d].y * T.invk;
                    v[d].z += s[d].z * T.invk; v[d].w += s[d].w * T.invk;
                }
            }
        } else {
            #pragma unroll
            for (int d = 0; d < 8; d++) v[d] = make_float4(0.f,0.f,0.f,0.f);
        }
        #pragma unroll
        for (int d = 0; d < 8; d++)
            *(float4*)(sIn + lr*132 + part*32 + d*4) = v[d];
    }
    __syncthreads();

    // 64x128 GEMM: thread tile 4 rows x 8 cols, packed f32x2
    const int r0 = (tid >> 4) * 4;
    const int c0 = (tid & 15) * 8;
    ull acc[4][4];
    #pragma unroll
    for (int i = 0; i < 4; i++)
        #pragma unroll
        for (int j = 0; j < 4; j++) acc[i][j] = 0ull;

    #pragma unroll 4
    for (int k = 0; k < kD; k++) {
        ull a0 = pack2(sIn[(r0+0)*132 + k]);
        ull a1 = pack2(sIn[(r0+1)*132 + k]);
        ull a2 = pack2(sIn[(r0+2)*132 + k]);
        ull a3 = pack2(sIn[(r0+3)*132 + k]);
        ulonglong2 b0 = *(const ulonglong2*)(sW + k*kD + c0);
        ulonglong2 b1 = *(const ulonglong2*)(sW + k*kD + c0 + 4);
        acc[0][0]=fma2(a0,b0.x,acc[0][0]); acc[0][1]=fma2(a0,b0.y,acc[0][1]);
        acc[0][2]=fma2(a0,b1.x,acc[0][2]); acc[0][3]=fma2(a0,b1.y,acc[0][3]);
        acc[1][0]=fma2(a1,b0.x,acc[1][0]); acc[1][1]=fma2(a1,b0.y,acc[1][1]);
        acc[1][2]=fma2(a1,b1.x,acc[1][2]); acc[1][3]=fma2(a1,b1.y,acc[1][3]);
        acc[2][0]=fma2(a2,b0.x,acc[2][0]); acc[2][1]=fma2(a2,b0.y,acc[2][1]);
        acc[2][2]=fma2(a2,b1.x,acc[2][2]); acc[2][3]=fma2(a2,b1.y,acc[2][3]);
        acc[3][0]=fma2(a3,b0.x,acc[3][0]); acc[3][1]=fma2(a3,b0.y,acc[3][1]);
        acc[3][2]=fma2(a3,b1.x,acc[3][2]); acc[3][3]=fma2(a3,b1.y,acc[3][3]);
    }

    float bsv[8];
    #pragma unroll
    for (int j = 0; j < 8; j++) bsv[j] = __ldg(&T.bias[c0 + j]);

    #pragma unroll
    for (int i = 0; i < 4; i++) {
        int gr = row0 + r0 + i;
        if (gr >= T.R) continue;
        float o[8];
        #pragma unroll
        for (int pi = 0; pi < 4; pi++) {
            float2 u = unpack2(acc[i][pi]);
            o[2*pi]   = fast_tanh(u.x + bsv[2*pi]);
            o[2*pi+1] = fast_tanh(u.y + bsv[2*pi+1]);
        }
        *(float4*)(T.out + (size_t)gr*kD + c0)     = make_float4(o[0],o[1],o[2],o[3]);
        *(float4*)(T.out + (size_t)gr*kD + c0 + 4) = make_float4(o[4],o[5],o[6],o[7]);
    }
}

// ---------------- fused level2 + last projection (512 thr, 64 rows, 2x8 packed) ----------------
__global__ __launch_bounds__(512, 1) void hop2_kernel(
    const int* __restrict__ q_nbr,
    const float* __restrict__ aggW, const float* __restrict__ aggb,
    const float* __restrict__ lastW, const float* __restrict__ lastb)
{
    extern __shared__ float sm[];
    float* sW1 = sm;                     // agg_W[0]
    float* sW2 = sm + kD*kD;             // last_W
    float* sIn = sm + 2*kD*kD;           // 64x132
    const int tid = threadIdx.x;

    const float* TB0 = g_buf + O_TB0;
    const float* TB1 = g_buf + O_TB1;
    float* A = g_buf + O_A;

    {
        const float4* W1p = (const float4*)aggW;
        const float4* W2p = (const float4*)lastW;
        #pragma unroll
        for (int i = 0; i < 8; i++) {
            ((float4*)sW1)[tid + i*512] = __ldg(&W1p[tid + i*512]);
            ((float4*)sW2)[tid + i*512] = __ldg(&W2p[tid + i*512]);
        }
    }

    const int row0 = blockIdx.x * 64;

    // gather: TB0[r] + mean_j TB1[q_nbr[r][j]]  (8 thr/row, 16 dims = 4 float4)
    {
        int lr = tid >> 3, part = tid & 7;
        int gr = row0 + lr;
        float4 v[4];
        if (gr < kNQ) {
            const float4* bp = (const float4*)(TB0 + (size_t)gr*kD) + part*4;
            #pragma unroll
            for (int d = 0; d < 4; d++) v[d] = bp[d];
            float4 s[4];
            #pragma unroll
            for (int d = 0; d < 4; d++) s[d] = make_float4(0.f,0.f,0.f,0.f);
            #pragma unroll
            for (int j = 0; j < kQN; j++) {
                int nb = __ldg(&q_nbr[(size_t)gr*kQN + j]);
                const float4* tp = (const float4*)(TB1 + (size_t)nb*kD) + part*4;
                #pragma unroll
                for (int d = 0; d < 4; d++) {
                    float4 x = tp[d];
                    s[d].x += x.x; s[d].y += x.y; s[d].z += x.z; s[d].w += x.w;
                }
            }
            const float iq = 1.f/kQN;
            #pragma unroll
            for (int d = 0; d < 4; d++) {
                v[d].x += s[d].x*iq; v[d].y += s[d].y*iq;
                v[d].z += s[d].z*iq; v[d].w += s[d].w*iq;
            }
        } else {
            #pragma unroll
            for (int d = 0; d < 4; d++) v[d] = make_float4(0.f,0.f,0.f,0.f);
        }
        #pragma unroll
        for (int d = 0; d < 4; d++)
            *(float4*)(sIn + lr*132 + part*16 + d*4) = v[d];
    }
    __syncthreads();

    const int r0 = (tid >> 4) * 2;
    const int c0 = (tid & 15) * 8;
    ull acc[2][4];
    float ab[8], lb[8];
    #pragma unroll
    for (int j = 0; j < 8; j++) { ab[j] = __ldg(&aggb[c0+j]); lb[j] = __ldg(&lastb[c0+j]); }

    // GEMM 1: tanh(x @ agg_W0 + agg_b0) -> sIn
    #pragma unroll
    for (int i = 0; i < 2; i++)
        #pragma unroll
        for (int j = 0; j < 4; j++) acc[i][j] = 0ull;
    #pragma unroll 4
    for (int k = 0; k < kD; k++) {
        ull a0 = pack2(sIn[(r0+0)*132 + k]);
        ull a1 = pack2(sIn[(r0+1)*132 + k]);
        ulonglong2 b0 = *(const ulonglong2*)(sW1 + k*kD + c0);
        ulonglong2 b1 = *(const ulonglong2*)(sW1 + k*kD + c0 + 4);
        acc[0][0]=fma2(a0,b0.x,acc[0][0]); acc[0][1]=fma2(a0,b0.y,acc[0][1]);
        acc[0][2]=fma2(a0,b1.x,acc[0][2]); acc[0][3]=fma2(a0,b1.y,acc[0][3]);
        acc[1][0]=fma2(a1,b0.x,acc[1][0]); acc[1][1]=fma2(a1,b0.y,acc[1][1]);
        acc[1][2]=fma2(a1,b1.x,acc[1][2]); acc[1][3]=fma2(a1,b1.y,acc[1][3]);
    }
    __syncthreads();
    #pragma unroll
    for (int i = 0; i < 2; i++)
        #pragma unroll
        for (int pi = 0; pi < 4; pi++) {
            float2 u = unpack2(acc[i][pi]);
            sIn[(r0+i)*132 + c0 + 2*pi]   = fast_tanh(u.x + ab[2*pi]);
            sIn[(r0+i)*132 + c0 + 2*pi+1] = fast_tanh(u.y + ab[2*pi+1]);
        }
    __syncthreads();

    // GEMM 2: tanh(y @ last_W + last_b) -> A
    #pragma unroll
    for (int i = 0; i < 2; i++)
        #pragma unroll
        for (int j = 0; j < 4; j++) acc[i][j] = 0ull;
    #pragma unroll 4
    for (int k = 0; k < kD; k++) {
        ull a0 = pack2(sIn[(r0+0)*132 + k]);
        ull a1 = pack2(sIn[(r0+1)*132 + k]);
        ulonglong2 b0 = *(const ulonglong2*)(sW2 + k*kD + c0);
        ulonglong2 b1 = *(const ulonglong2*)(sW2 + k*kD + c0 + 4);
        acc[0][0]=fma2(a0,b0.x,acc[0][0]); acc[0][1]=fma2(a0,b0.y,acc[0][1]);
        acc[0][2]=fma2(a0,b1.x,acc[0][2]); acc[0][3]=fma2(a0,b1.y,acc[0][3]);
        acc[1][0]=fma2(a1,b0.x,acc[1][0]); acc[1][1]=fma2(a1,b0.y,acc[1][1]);
        acc[1][2]=fma2(a1,b1.x,acc[1][2]); acc[1][3]=fma2(a1,b1.y,acc[1][3]);
    }
    #pragma unroll
    for (int i = 0; i < 2; i++) {
        int gr = row0 + r0 + i;
        if (gr >= kNQ) continue;
        float o[8];
        #pragma unroll
        for (int pi = 0; pi < 4; pi++) {
            float2 u = unpack2(acc[i][pi]);
            o[2*pi]   = fast_tanh(u.x + lb[2*pi]);
            o[2*pi+1] = fast_tanh(u.y + lb[2*pi+1]);
        }
        *(float4*)(A + (size_t)gr*kD + c0)     = make_float4(o[0],o[1],o[2],o[3]);
        *(float4*)(A + (size_t)gr*kD + c0 + 4) = make_float4(o[4],o[5],o[6],o[7]);
    }
}

// ---------------- fused row chain: QT -> gates -> h -> a_state (256 thr, 32 rows, 2x8) ----------------
__device__ __forceinline__ void gemm2x8p(const float* __restrict__ sIn,
                                         const float* __restrict__ sW,
                                         ull acc[2][4], int r0, int c0)
{
    #pragma unroll
    for (int i = 0; i < 2; i++)
        #pragma unroll
        for (int j = 0; j < 4; j++) acc[i][j] = 0ull;
    #pragma unroll 4
    for (int k = 0; k < kD; k++) {
        ull a0 = pack2(sIn[(r0+0)*132 + k]);
        ull a1 = pack2(sIn[(r0+1)*132 + k]);
        ulonglong2 b0 = *(const ulonglong2*)(sW + k*kD + c0);
        ulonglong2 b1 = *(const ulonglong2*)(sW + k*kD + c0 + 4);
        acc[0][0]=fma2(a0,b0.x,acc[0][0]); acc[0][1]=fma2(a0,b0.y,acc[0][1]);
        acc[0][2]=fma2(a0,b1.x,acc[0][2]); acc[0][3]=fma2(a0,b1.y,acc[0][3]);
        acc[1][0]=fma2(a1,b0.x,acc[1][0]); acc[1][1]=fma2(a1,b0.y,acc[1][1]);
        acc[1][2]=fma2(a1,b1.x,acc[1][2]); acc[1][3]=fma2(a1,b1.y,acc[1][3]);
    }
}

__device__ __forceinline__ void loadW256(float* sW, const float* __restrict__ W,
                                         int ldw, int tid)
{
    for (int i = tid; i < kD*32; i += 256) {
        int k = i >> 5, c4 = i & 31;
        ((float4*)(sW + k*kD))[c4] = __ldg(&((const float4*)(W + (size_t)k*ldw))[c4]);
    }
}

__global__ __launch_bounds__(256, 2) void rowchain_kernel(
    const int* __restrict__ question, const int* __restrict__ response,
    const float* __restrict__ ft_W, const float* __restrict__ ft_b,
    const float* __restrict__ W_ih)
{
    extern __shared__ float sm[];
    float* sW  = sm;               // 128x128
    float* sIn = sm + kD*kD;       // 32x132
    float* sC  = sIn + 32*132;     // 32x132
    float* sqv = sC + 32*132;      // 128

    const float* A   = g_buf + O_A;
    const float* vec = g_buf + O_V;
    const float* RG  = g_buf + O_RG;
    float* H  = g_buf + O_H;
    float* AS = g_buf + O_AS;

    const int tid = threadIdx.x;
    const int row0 = blockIdx.x * 32;
    if (tid < kD) sqv[tid] = vec[tid];

    // gather A[question[row]] (8 threads/row, 16 dims = 4 float4)
    {
        int lr = tid >> 3, part = tid & 7;
        int grow = row0 + lr;
        int q = __ldg(&question[grow]);
        const float4* ap = (const float4*)(A + (size_t)q*kD) + part*4;
        #pragma unroll
        for (int d = 0; d < 4; d++)
            *(float4*)(sIn + lr*132 + part*16 + d*4) = ap[d];
    }
    loadW256(sW, ft_W, kD, tid);
    __syncthreads();

    const int r0 = (tid >> 4) * 2;
    const int c0 = (tid & 15) * 8;
    ull acc[2][4];
    const int resp0 = __ldg(&response[row0 + r0]);
    const int resp1 = __ldg(&response[row0 + r0 + 1]);

    // stage 1: QT = relu(in @ ft_W + ft_b)
    gemm2x8p(sIn, sW, acc, r0, c0);
    float fb[8];
    #pragma unroll
    for (int j = 0; j < 8; j++) fb[j] = __ldg(&ft_b[c0 + j]);
    __syncthreads();
    #pragma unroll
    for (int i = 0; i < 2; i++)
        #pragma unroll
        for (int pi = 0; pi < 4; pi++) {
            float2 u = unpack2(acc[i][pi]);
            sIn[(r0+i)*132 + c0 + 2*pi]   = fmaxf(u.x + fb[2*pi],   0.f);
            sIn[(r0+i)*132 + c0 + 2*pi+1] = fmaxf(u.y + fb[2*pi+1], 0.f);
        }
    loadW256(sW, W_ih + 0, 512, tid);       // i-gate cols
    __syncthreads();

    // stage 2: i gate -> sigmoid -> sC
    gemm2x8p(sIn, sW, acc, r0, c0);
    #pragma unroll
    for (int i = 0; i < 2; i++) {
        int rr = i ? resp1 : resp0;
        #pragma unroll
        for (int pi = 0; pi < 4; pi++) {
            float2 u = unpack2(acc[i][pi]);
            sC[(r0+i)*132 + c0 + 2*pi]   = fast_sigmoid(u.x + RG[rr*512 + c0 + 2*pi]);
            sC[(r0+i)*132 + c0 + 2*pi+1] = fast_sigmoid(u.y + RG[rr*512 + c0 + 2*pi+1]);
        }
    }
    __syncthreads();
    loadW256(sW, W_ih + 256, 512, tid);     // g-gate cols
    __syncthreads();

    // stage 3: g gate -> tanh(c), c = sig(i)*tanh(g)
    gemm2x8p(sIn, sW, acc, r0, c0);
    #pragma unroll
    for (int i = 0; i < 2; i++) {
        int rr = i ? resp1 : resp0;
        #pragma unroll
        for (int pi = 0; pi < 4; pi++) {
            float2 u = unpack2(acc[i][pi]);
            float g0 = u.x + RG[rr*512 + 256 + c0 + 2*pi];
            float g1 = u.y + RG[rr*512 + 256 + c0 + 2*pi+1];
            float c0v = sC[(r0+i)*132 + c0 + 2*pi]   * fast_tanh(g0);
            float c1v = sC[(r0+i)*132 + c0 + 2*pi+1] * fast_tanh(g1);
            sC[(r0+i)*132 + c0 + 2*pi]   = fast_tanh(c0v);
            sC[(r0+i)*132 + c0 + 2*pi+1] = fast_tanh(c1v);
        }
    }
    __syncthreads();
    loadW256(sW, W_ih + 384, 512, tid);     // o-gate cols
    __syncthreads();

    // stage 4: o gate -> h = sig(o)*tanh(c)
    gemm2x8p(sIn, sW, acc, r0, c0);
    #pragma unroll
    for (int i = 0; i < 2; i++) {
        int rr = i ? resp1 : resp0;
        int grow = row0 + r0 + i;
        float hv[8];
        #pragma unroll
        for (int pi = 0; pi < 4; pi++) {
            float2 u = unpack2(acc[i][pi]);
            float o0 = u.x + RG[rr*512 + 384 + c0 + 2*pi];
            float o1 = u.y + RG[rr*512 + 384 + c0 + 2*pi+1];
            hv[2*pi]   = fast_sigmoid(o0) * sC[(r0+i)*132 + c0 + 2*pi];
            hv[2*pi+1] = fast_sigmoid(o1) * sC[(r0+i)*132 + c0 + 2*pi+1];
            sC[(r0+i)*132 + c0 + 2*pi]   = hv[2*pi];
            sC[(r0+i)*132 + c0 + 2*pi+1] = hv[2*pi+1];
        }
        *(float4*)(H + (size_t)grow*kD + c0)     = make_float4(hv[0],hv[1],hv[2],hv[3]);
        *(float4*)(H + (size_t)grow*kD + c0 + 4) = make_float4(hv[4],hv[5],hv[6],hv[7]);
    }
    __syncthreads();

    // a_state = h . qv + c_q  (8 threads/row, 16 dims each)
    {
        int lr = tid >> 3, part = tid & 7;
        int grow = row0 + lr;
        int b = grow / kS, s = grow % kS;
        float p = 0.f;
        #pragma unroll
        for (int d = 0; d < 16; d++)
            p += sC[lr*132 + part*16 + d] * sqv[part*16 + d];
        p += __shfl_down_sync(0xffffffffu, p, 4);
        p += __shfl_down_sync(0xffffffffu, p, 2);
        p += __shfl_down_sync(0xffffffffu, p, 1);
        if (part == 0 && s < kT)
            AS[b*kT + s] = p + vec[256];
    }
}

// ---------------- fused attention + prediction ----------------
// 8 warps/block share one b and 8 adjacent t -> h[b] stays L1-resident.
__global__ __launch_bounds__(256, 2) void pred_kernel(
    const int* __restrict__ question,
    const int* __restrict__ qs_skills,
    const float* __restrict__ emb_q,
    const float* __restrict__ emb_s,
    float* __restrict__ out)
{
    __shared__ __align__(16) float sqs[8][5][kD];

    const float* vec = g_buf + O_V;
    const int b = blockIdx.y;
    const int w = threadIdx.x >> 5;
    const int lane = threadIdx.x & 31;
    const int t = 198 - ((int)blockIdx.x * 8 + w);   // big t first
    if (t < 0) return;

    const float* asb = g_buf + O_AS + b*kT;
    const float* hb  = g_buf + O_H  + (size_t)b*kS*kD;

    int q = __ldg(&question[b*kS + t + 1]);
    ((float4*)sqs[w][0])[lane] = __ldg((const float4*)(emb_q + (size_t)q*kD) + lane);
    #pragma unroll
    for (int m = 1; m < 5; m++) {
        int si = __ldg(&qs_skills[q*4 + m - 1]);
        ((float4*)sqs[w][m])[lane] = __ldg((const float4*)(emb_s + (size_t)si*kD) + lane);
    }
    __syncwarp();

    // a_qs[m] = dot(sqs[m], kv); softmax over m (c_k cancels)
    float4 kv4 = *((const float4*)(vec + kD) + lane);
    float r[5];
    #pragma unroll
    for (int m = 0; m < 5; m++) {
        float4 s4 = ((float4*)sqs[w][m])[lane];
        float p = s4.x*kv4.x + s4.y*kv4.y + s4.z*kv4.z + s4.w*kv4.w;
        #pragma unroll
        for (int o = 16; o; o >>= 1) p += __shfl_xor_sync(0xffffffffu, p, o);
        r[m] = p;
    }
    {
        float mx = r[0];
        #pragma unroll
        for (int m = 1; m < 5; m++) mx = fmaxf(mx, r[m]);
        float se = 0.f;
        #pragma unroll
        for (int m = 0; m < 5; m++) { r[m] = __expf(r[m] - mx); se += r[m]; }
        float inv = __frcp_rn(se);
        #pragma unroll
        for (int m = 0; m < 5; m++) r[m] *= inv;
    }

    // max of a_state over n<=t
    float M1 = -1e30f;
    for (int n = lane; n <= t; n += 32) M1 = fmaxf(M1, asb[n]);
    #pragma unroll
    for (int o = 16; o; o >>= 1) M1 = fmaxf(M1, __shfl_xor_sync(0xffffffffu, M1, o));

    float sum_v = 0.f, sum_e = 0.f;
    for (int base = 0; base <= t; base += 64) {
        int n1 = base + lane, n2 = n1 + 32;
        float e1 = (n1 <= t) ? __expf(asb[n1] - M1) : 0.f;
        float e2 = (n2 <= t) ? __expf(asb[n2] - M1) : 0.f;
        int np1 = n1 <= t ? n1 : t;
        int np2 = n2 <= t ? n2 : t;
        const ulonglong2* h1 = (const ulonglong2*)(hb + (size_t)np1*kD);
        const ulonglong2* h2 = (const ulonglong2*)(hb + (size_t)np2*kD);
        ull inA[5], inB[5];
        #pragma unroll
        for (int m = 0; m < 5; m++) { inA[m] = 0ull; inB[m] = 0ull; }
        // full D=128: 32 chunks of 4 floats (ulonglong2 = 2x f32x2)
        #pragma unroll
        for (int c = 0; c < 32; c++) {
            ulonglong2 a1 = h1[c];
            ulonglong2 a2 = h2[c];
            #pragma unroll
            for (int m = 0; m < 5; m++) {
                ulonglong2 s = *(const ulonglong2*)&sqs[w][m][c*4];
                inA[m] = fma2(a1.x, s.x, inA[m]);
                inA[m] = fma2(a1.y, s.y, inA[m]);
                inB[m] = fma2(a2.x, s.x, inB[m]);
                inB[m] = fma2(a2.y, s.y, inB[m]);
            }
        }
        float sv1 = 0.f, sv2 = 0.f;
        #pragma unroll
        for (int m = 0; m < 5; m++) {
            float2 pa = unpack2(inA[m]);
            float2 pb = unpack2(inB[m]);
            sv1 += r[m] * fast_sigmoid(pa.x + pa.y);
            sv2 += r[m] * fast_sigmoid(pb.x + pb.y);
        }
        sum_v += e1*sv1 + e2*sv2;
        sum_e += e1 + e2;
    }
    #pragma unroll
    for (int o = 16; o; o >>= 1) {
        sum_v += __shfl_xor_sync(0xffffffffu, sum_v, o);
        sum_e += __shfl_xor_sync(0xffffffffu, sum_e, o);
    }
    if (lane == 0) {
        out[b*kS + t + 1] = sum_v / sum_e;
        if (t == 0) out[b*kS] = 0.f;
    }
}

// ---------------- launch ----------------
extern "C" void kernel_launch(void* const* d_in, const int* in_sizes, int n_in,
                              void* d_out, int out_size)
{
    const int*   question = (const int*)  d_in[0];
    const int*   response = (const int*)  d_in[1];
    const int*   q_nbr    = (const int*)  d_in[3];
    const int*   s_nbr    = (const int*)  d_in[4];
    const int*   qs_sk    = (const int*)  d_in[5];
    const float* emb_q    = (const float*)d_in[6];
    const float* emb_s    = (const float*)d_in[7];
    const float* emb_r    = (const float*)d_in[8];
    const float* W_ih     = (const float*)d_in[9];
    const float* b_ih     = (const float*)d_in[10];
    const float* b_hh     = (const float*)d_in[11];
    const float* ft_W     = (const float*)d_in[12];
    const float* ft_b     = (const float*)d_in[13];
    const float* agg_W    = (const float*)d_in[14];
    const float* agg_b    = (const float*)d_in[15];
    const float* last_W   = (const float*)d_in[16];
    const float* last_b   = (const float*)d_in[17];
    const float* q_W      = (const float*)d_in[18];
    const float* q_b      = (const float*)d_in[19];
    const float* k_W      = (const float*)d_in[20];
    const float* k_b      = (const float*)d_in[21];
    const float* w_W      = (const float*)d_in[22];
    float* out = (float*)d_out;

    float* buf = nullptr;
    cudaGetSymbolAddress((void**)&buf, g_buf);
    float* TA0 = buf + O_TA0;
    float* TA1 = buf + O_TA1;
    float* TA2 = buf + O_TA2;
    float* TB0 = buf + O_TB0;
    float* TB1 = buf + O_TB1;

    const int HOP_SMEM  = (kD*kD   + 64*132) * (int)sizeof(float);
    const int HOP2_SMEM = (2*kD*kD + 64*132) * (int)sizeof(float);
    const int RC_SMEM   = (kD*kD + 2*32*132 + 128) * (int)sizeof(float);
    static bool attr_done = false;
    if (!attr_done) {
        cudaFuncSetAttribute(hop_kernel,      cudaFuncAttributeMaxDynamicSharedMemorySize, HOP_SMEM);
        cudaFuncSetAttribute(hop2_kernel,     cudaFuncAttributeMaxDynamicSharedMemorySize, HOP2_SMEM);
        cudaFuncSetAttribute(rowchain_kernel, cudaFuncAttributeMaxDynamicSharedMemorySize, RC_SMEM);
        attr_done = true;
    }

    const int gq = (kNQ + 63) / 64;        // 157
    const int gs = (kNS + 63) / 64;        // 8
    const float iq = 1.f/kQN, is = 1.f/kSN;

    PrepArgs noprep = {}; noprep.enable = 0;

    // level 0: TA0, TA2, TA1  (+ prep block)
    {
        HopParams p;
        p.nt = 3;
        p.t[0] = { emb_q, q_nbr, emb_s, agg_W,           agg_b,       TA0, kQN, iq, kNQ, 0 };
        p.t[1] = { emb_q, q_nbr, emb_s, agg_W + 2*16384, agg_b + 256, TA2, kQN, iq, kNQ, gq };
        p.t[2] = { emb_s, s_nbr, emb_q, agg_W + 16384,   agg_b + 128, TA1, kSN, is, kNS, 2*gq };
        p.prep = { q_W, q_b, k_W, k_b, w_W, emb_r, W_ih, b_ih, b_hh, 1 };
        hop_kernel<<<2*gq + gs + 1, 256, HOP_SMEM>>>(p);
    }
    // level 1: TB0, TB1
    {
        HopParams p;
        p.nt = 2;
        p.t[0] = { TA0, q_nbr, TA1, agg_W,         agg_b,       TB0, kQN, iq, kNQ, 0 };
        p.t[1] = { TA1, s_nbr, TA2, agg_W + 16384, agg_b + 128, TB1, kSN, is, kNS, gq };
        p.t[2] = p.t[1];
        p.prep = noprep;
        hop_kernel<<<gq + gs, 256, HOP_SMEM>>>(p);
    }
    // level 2 + last projection fused -> A
    hop2_kernel<<<gq, 512, HOP2_SMEM>>>(q_nbr, agg_W, agg_b, last_W, last_b);

    rowchain_kernel<<<(kB*kS)/32, 256, RC_SMEM>>>(question, response, ft_W, ft_b, W_ih);

    dim3 pg(25, kB);
    pred_kernel<<<pg, 256>>>(question, qs_sk, emb_q, emb_s, out);
}

// round 6
// speedup vs baseline: 1.7262x; 1.7262x over previous
#include <cuda_runtime.h>
#include <math.h>
#include <stdint.h>

// ---------------- problem constants ----------------
#define kNQ 10000
#define kNS 500
#define kQN 4
#define kSN 10
#define kB  32
#define kS  200
#define kD  128
#define kT  199   // S-1

// ---------------- scratch layout (floats) ----------------
__host__ __device__ constexpr size_t O_TA0 = 0;
__host__ __device__ constexpr size_t O_TA1 = O_TA0 + (size_t)kNQ*kD;
__host__ __device__ constexpr size_t O_TA2 = O_TA1 + (size_t)kNS*kD;
__host__ __device__ constexpr size_t O_TB0 = O_TA2 + (size_t)kNQ*kD;
__host__ __device__ constexpr size_t O_TB1 = O_TB0 + (size_t)kNQ*kD;
__host__ __device__ constexpr size_t O_A   = O_TB1 + (size_t)kNS*kD;
__host__ __device__ constexpr size_t O_H   = O_A   + (size_t)kNQ*kD;
__host__ __device__ constexpr size_t O_AS  = O_H   + (size_t)kB*kS*kD;
__host__ __device__ constexpr size_t O_V   = O_AS  + (size_t)kB*kT;   // qv[128], kv[128], c_q, c_k
__host__ __device__ constexpr size_t O_RG  = O_V   + 258;             // r_gates 2x512
__host__ __device__ constexpr size_t G_TOTAL = O_RG + 1024;

__device__ float g_buf[G_TOTAL];

// ---------------- fast math ----------------
__device__ __forceinline__ float fast_tanh(float x) {
    float y;
    asm("tanh.approx.f32 %0, %1;" : "=f"(y) : "f"(x));
    return y;
}
__device__ __forceinline__ float fast_sigmoid(float x) {
    return 0.5f * fast_tanh(0.5f * x) + 0.5f;
}

// ---------------- task structs ----------------
struct HopTask {
    const float* base;
    const int*   nbrs;
    const float* tbl;
    const float* W;
    const float* bias;
    float*       out;
    int knbr; float invk;
    int R; int blk0;
};
struct PrepArgs {
    const float *qW, *qb, *kW, *kb, *wW, *embr, *Wih, *bih, *bhh;
    int enable;
};
struct HopParams { HopTask t[3]; int nt; PrepArgs prep; };

// ---------------- fused multi-task hop kernel (512 thr, 64 rows, 2x8 scalar) ----------------
__global__ __launch_bounds__(512, 2) void hop_kernel(const HopParams p)
{
    extern __shared__ float sm[];
    float* sW  = sm;                 // 128x128
    float* sIn = sm + kD*kD;         // 64x132
    const int tid = threadIdx.x;

    // prep block (independent side-work; consumers run 3 kernels later)
    if (p.prep.enable && blockIdx.x == (int)gridDim.x - 1) {
        const PrepArgs& A = p.prep;
        float* vec = g_buf + O_V;
        float* rg  = g_buf + O_RG;
        int t = tid;
        if (t < kD) {
            float sq = 0.f, sk = 0.f;
            #pragma unroll 4
            for (int j = 0; j < kD; j++) {
                sq += A.qW[t*kD + j] * A.wW[j];
                sk += A.kW[t*kD + j] * A.wW[kD + j];
            }
            vec[t]      = sq;
            vec[kD + t] = sk;
        }
        if (t == 256) {
            float s = 0.f;
            for (int j = 0; j < kD; j++) s += A.qb[j] * A.wW[j];
            vec[256] = s;
        }
        if (t == 257) {
            float s = 0.f;
            for (int j = 0; j < kD; j++) s += A.kb[j] * A.wW[kD + j];
            vec[257] = s;
        }
        if (t < 512) {
            for (int r = 0; r < 2; r++) {
                float s = A.bih[t] + A.bhh[t];
                #pragma unroll 4
                for (int k = 0; k < kD; k++)
                    s += A.embr[r*kD + k] * A.Wih[(size_t)(kD + k)*512 + t];
                rg[r*512 + t] = s;
            }
        }
        return;
    }

    int ti = 0;
    #pragma unroll
    for (int i = 1; i < 3; i++)
        if (i < p.nt && (int)blockIdx.x >= p.t[i].blk0) ti = i;
    const HopTask& T = p.t[ti];
    const int row0 = (blockIdx.x - T.blk0) * 64;

    // load W (128x128): 4096 float4 / 512 thr
    {
        const float4* Wp = (const float4*)T.W;
        #pragma unroll
        for (int i = 0; i < 8; i++)
            ((float4*)sW)[tid + i*512] = __ldg(&Wp[tid + i*512]);
    }

    // build 64 input rows (8 threads/row, 16 dims = 4 float4 each)
    {
        int lr = tid >> 3, part = tid & 7;
        int gr = row0 + lr;
        float4 v[4];
        if (gr < T.R) {
            const float4* bp = (const float4*)(T.base + (size_t)gr*kD) + part*4;
            #pragma unroll
            for (int d = 0; d < 4; d++) v[d] = __ldg(&bp[d]);
            if (T.knbr > 0) {
                float4 s[4];
                #pragma unroll
                for (int d = 0; d < 4; d++) s[d] = make_float4(0.f,0.f,0.f,0.f);
                for (int j = 0; j < T.knbr; j++) {
                    int nb = __ldg(&T.nbrs[(size_t)gr*T.knbr + j]);
                    const float4* tp = (const float4*)(T.tbl + (size_t)nb*kD) + part*4;
                    #pragma unroll
                    for (int d = 0; d < 4; d++) {
                        float4 x = __ldg(&tp[d]);
                        s[d].x += x.x; s[d].y += x.y; s[d].z += x.z; s[d].w += x.w;
                    }
                }
                #pragma unroll
                for (int d = 0; d < 4; d++) {
                    v[d].x += s[d].x * T.invk; v[d].y += s[d].y * T.invk;
                    v[d].z += s[d].z * T.invk; v[d].w += s[d].w * T.invk;
                }
            }
        } else {
            #pragma unroll
            for (int d = 0; d < 4; d++) v[d] = make_float4(0.f,0.f,0.f,0.f);
        }
        #pragma unroll
        for (int d = 0; d < 4; d++)
            *(float4*)(sIn + lr*132 + part*16 + d*4) = v[d];
    }
    __syncthreads();

    // 64x128 GEMM: thread tile 2 rows x 8 cols (scalar)
    const int r0 = (tid >> 4) * 2;
    const int c0 = (tid & 15) * 8;
    float acc[2][8];
    #pragma unroll
    for (int i = 0; i < 2; i++)
        #pragma unroll
        for (int j = 0; j < 8; j++) acc[i][j] = 0.f;

    #pragma unroll 4
    for (int k = 0; k < kD; k++) {
        float a0 = sIn[(r0+0)*132 + k];
        float a1 = sIn[(r0+1)*132 + k];
        float4 b0 = *(const float4*)(sW + k*kD + c0);
        float4 b1 = *(const float4*)(sW + k*kD + c0 + 4);
        float bb[8] = {b0.x,b0.y,b0.z,b0.w,b1.x,b1.y,b1.z,b1.w};
        #pragma unroll
        for (int j = 0; j < 8; j++) {
            acc[0][j] += a0*bb[j];
            acc[1][j] += a1*bb[j];
        }
    }

    float bsv[8];
    #pragma unroll
    for (int j = 0; j < 8; j++) bsv[j] = __ldg(&T.bias[c0 + j]);

    #pragma unroll
    for (int i = 0; i < 2; i++) {
        int gr = row0 + r0 + i;
        if (gr >= T.R) continue;
        float4 o0, o1;
        o0.x = fast_tanh(acc[i][0] + bsv[0]); o0.y = fast_tanh(acc[i][1] + bsv[1]);
        o0.z = fast_tanh(acc[i][2] + bsv[2]); o0.w = fast_tanh(acc[i][3] + bsv[3]);
        o1.x = fast_tanh(acc[i][4] + bsv[4]); o1.y = fast_tanh(acc[i][5] + bsv[5]);
        o1.z = fast_tanh(acc[i][6] + bsv[6]); o1.w = fast_tanh(acc[i][7] + bsv[7]);
        *(float4*)(T.out + (size_t)gr*kD + c0)     = o0;
        *(float4*)(T.out + (size_t)gr*kD + c0 + 4) = o1;
    }
}

// ---------------- fused level2 + last projection (512 thr, 64 rows, 2x8 scalar) ----------------
__global__ __launch_bounds__(512, 1) void hop2_kernel(
    const int* __restrict__ q_nbr,
    const float* __restrict__ aggW, const float* __restrict__ aggb,
    const float* __restrict__ lastW, const float* __restrict__ lastb)
{
    extern __shared__ float sm[];
    float* sW1 = sm;                     // agg_W[0]
    float* sW2 = sm + kD*kD;             // last_W
    float* sIn = sm + 2*kD*kD;           // 64x132
    const int tid = threadIdx.x;

    const float* TB0 = g_buf + O_TB0;
    const float* TB1 = g_buf + O_TB1;
    float* A = g_buf + O_A;

    {
        const float4* W1p = (const float4*)aggW;
        const float4* W2p = (const float4*)lastW;
        #pragma unroll
        for (int i = 0; i < 8; i++) {
            ((float4*)sW1)[tid + i*512] = __ldg(&W1p[tid + i*512]);
            ((float4*)sW2)[tid + i*512] = __ldg(&W2p[tid + i*512]);
        }
    }

    const int row0 = blockIdx.x * 64;

    // gather: TB0[r] + mean_j TB1[q_nbr[r][j]]  (8 thr/row, 16 dims = 4 float4)
    {
        int lr = tid >> 3, part = tid & 7;
        int gr = row0 + lr;
        float4 v[4];
        if (gr < kNQ) {
            const float4* bp = (const float4*)(TB0 + (size_t)gr*kD) + part*4;
            #pragma unroll
            for (int d = 0; d < 4; d++) v[d] = bp[d];
            float4 s[4];
            #pragma unroll
            for (int d = 0; d < 4; d++) s[d] = make_float4(0.f,0.f,0.f,0.f);
            #pragma unroll
            for (int j = 0; j < kQN; j++) {
                int nb = __ldg(&q_nbr[(size_t)gr*kQN + j]);
                const float4* tp = (const float4*)(TB1 + (size_t)nb*kD) + part*4;
                #pragma unroll
                for (int d = 0; d < 4; d++) {
                    float4 x = tp[d];
                    s[d].x += x.x; s[d].y += x.y; s[d].z += x.z; s[d].w += x.w;
                }
            }
            const float iq = 1.f/kQN;
            #pragma unroll
            for (int d = 0; d < 4; d++) {
                v[d].x += s[d].x*iq; v[d].y += s[d].y*iq;
                v[d].z += s[d].z*iq; v[d].w += s[d].w*iq;
            }
        } else {
            #pragma unroll
            for (int d = 0; d < 4; d++) v[d] = make_float4(0.f,0.f,0.f,0.f);
        }
        #pragma unroll
        for (int d = 0; d < 4; d++)
            *(float4*)(sIn + lr*132 + part*16 + d*4) = v[d];
    }
    __syncthreads();

    const int r0 = (tid >> 4) * 2;
    const int c0 = (tid & 15) * 8;
    float acc[2][8];
    float ab[8], lb[8];
    #pragma unroll
    for (int j = 0; j < 8; j++) { ab[j] = __ldg(&aggb[c0+j]); lb[j] = __ldg(&lastb[c0+j]); }

    // GEMM 1: tanh(x @ agg_W0 + agg_b0) -> sIn
    #pragma unroll
    for (int i = 0; i < 2; i++)
        #pragma unroll
        for (int j = 0; j < 8; j++) acc[i][j] = 0.f;
    #pragma unroll 4
    for (int k = 0; k < kD; k++) {
        float a0 = sIn[(r0+0)*132 + k];
        float a1 = sIn[(r0+1)*132 + k];
        float4 b0 = *(const float4*)(sW1 + k*kD + c0);
        float4 b1 = *(const float4*)(sW1 + k*kD + c0 + 4);
        float bb[8] = {b0.x,b0.y,b0.z,b0.w,b1.x,b1.y,b1.z,b1.w};
        #pragma unroll
        for (int j = 0; j < 8; j++) {
            acc[0][j] += a0*bb[j];
            acc[1][j] += a1*bb[j];
        }
    }
    __syncthreads();
    #pragma unroll
    for (int i = 0; i < 2; i++)
        #pragma unroll
        for (int j = 0; j < 8; j++)
            sIn[(r0+i)*132 + c0 + j] = fast_tanh(acc[i][j] + ab[j]);
    __syncthreads();

    // GEMM 2: tanh(y @ last_W + last_b) -> A
    #pragma unroll
    for (int i = 0; i < 2; i++)
        #pragma unroll
        for (int j = 0; j < 8; j++) acc[i][j] = 0.f;
    #pragma unroll 4
    for (int k = 0; k < kD; k++) {
        float a0 = sIn[(r0+0)*132 + k];
        float a1 = sIn[(r0+1)*132 + k];
        float4 b0 = *(const float4*)(sW2 + k*kD + c0);
        float4 b1 = *(const float4*)(sW2 + k*kD + c0 + 4);
        float bb[8] = {b0.x,b0.y,b0.z,b0.w,b1.x,b1.y,b1.z,b1.w};
        #pragma unroll
        for (int j = 0; j < 8; j++) {
            acc[0][j] += a0*bb[j];
            acc[1][j] += a1*bb[j];
        }
    }
    #pragma unroll
    for (int i = 0; i < 2; i++) {
        int gr = row0 + r0 + i;
        if (gr >= kNQ) continue;
        float4 o0, o1;
        o0.x = fast_tanh(acc[i][0] + lb[0]); o0.y = fast_tanh(acc[i][1] + lb[1]);
        o0.z = fast_tanh(acc[i][2] + lb[2]); o0.w = fast_tanh(acc[i][3] + lb[3]);
        o1.x = fast_tanh(acc[i][4] + lb[4]); o1.y = fast_tanh(acc[i][5] + lb[5]);
        o1.z = fast_tanh(acc[i][6] + lb[6]); o1.w = fast_tanh(acc[i][7] + lb[7]);
        *(float4*)(A + (size_t)gr*kD + c0)     = o0;
        *(float4*)(A + (size_t)gr*kD + c0 + 4) = o1;
    }
}

// ---------------- fused row chain: QT -> gates -> h -> a_state (R2 config: 256 thr, 32 rows, 2x8) ----------------
__device__ __forceinline__ void gemm32(const float* __restrict__ sIn,
                                       const float* __restrict__ sW,
                                       float acc[2][8], int r0, int c0)
{
    #pragma unroll
    for (int i = 0; i < 2; i++)
        #pragma unroll
        for (int j = 0; j < 8; j++) acc[i][j] = 0.f;
    #pragma unroll 4
    for (int k = 0; k < kD; k++) {
        float a0 = sIn[(r0+0)*132 + k];
        float a1 = sIn[(r0+1)*132 + k];
        float4 b0 = *(const float4*)(sW + k*kD + c0);
        float4 b1 = *(const float4*)(sW + k*kD + c0 + 4);
        float bb[8] = {b0.x,b0.y,b0.z,b0.w,b1.x,b1.y,b1.z,b1.w};
        #pragma unroll
        for (int j = 0; j < 8; j++) {
            acc[0][j] += a0*bb[j];
            acc[1][j] += a1*bb[j];
        }
    }
}

__device__ __forceinline__ void loadW256(float* sW, const float* __restrict__ W,
                                         int ldw, int tid)
{
    for (int i = tid; i < kD*32; i += 256) {
        int k = i >> 5, c4 = i & 31;
        ((float4*)(sW + k*kD))[c4] = __ldg(&((const float4*)(W + (size_t)k*ldw))[c4]);
    }
}

__global__ __launch_bounds__(256, 2) void rowchain_kernel(
    const int* __restrict__ question, const int* __restrict__ response,
    const float* __restrict__ ft_W, const float* __restrict__ ft_b,
    const float* __restrict__ W_ih)
{
    extern __shared__ float sm[];
    float* sW  = sm;               // 128x128
    float* sIn = sm + kD*kD;       // 32x132
    float* sC  = sIn + 32*132;     // 32x132
    float* sqv = sC + 32*132;      // 128

    const float* A   = g_buf + O_A;
    const float* vec = g_buf + O_V;
    const float* RG  = g_buf + O_RG;
    float* H  = g_buf + O_H;
    float* AS = g_buf + O_AS;

    const int tid = threadIdx.x;
    const int row0 = blockIdx.x * 32;
    if (tid < kD) sqv[tid] = vec[tid];

    // gather A[question[row]] into sIn (8 threads/row, 16 dims = 4 float4)
    {
        int lr = tid >> 3, part = tid & 7;
        int grow = row0 + lr;
        int q = __ldg(&question[grow]);
        const float4* ap = (const float4*)(A + (size_t)q*kD) + part*4;
        #pragma unroll
        for (int d = 0; d < 4; d++)
            *(float4*)(sIn + lr*132 + part*16 + d*4) = ap[d];
    }
    loadW256(sW, ft_W, kD, tid);
    __syncthreads();

    const int r0 = (tid >> 4) * 2;
    const int c0 = (tid & 15) * 8;
    float acc[2][8];
    const int resp0 = __ldg(&response[row0 + r0]);
    const int resp1 = __ldg(&response[row0 + r0 + 1]);

    // stage 1: QT = relu(in @ ft_W + ft_b)
    gemm32(sIn, sW, acc, r0, c0);
    float fb[8];
    #pragma unroll
    for (int j = 0; j < 8; j++) fb[j] = __ldg(&ft_b[c0 + j]);
    __syncthreads();
    #pragma unroll
    for (int i = 0; i < 2; i++)
        #pragma unroll
        for (int j = 0; j < 8; j++)
            sIn[(r0+i)*132 + c0 + j] = fmaxf(acc[i][j] + fb[j], 0.f);
    loadW256(sW, W_ih + 0, 512, tid);       // i-gate cols
    __syncthreads();

    // stage 2: i gate -> sigmoid -> sC
    gemm32(sIn, sW, acc, r0, c0);
    #pragma unroll
    for (int i = 0; i < 2; i++) {
        int rr = i ? resp1 : resp0;
        #pragma unroll
        for (int j = 0; j < 8; j++)
            sC[(r0+i)*132 + c0 + j] = fast_sigmoid(acc[i][j] + RG[rr*512 + 0 + c0 + j]);
    }
    __syncthreads();
    loadW256(sW, W_ih + 256, 512, tid);     // g-gate cols
    __syncthreads();

    // stage 3: g gate -> tanh(c), c = sig(i)*tanh(g)
    gemm32(sIn, sW, acc, r0, c0);
    #pragma unroll
    for (int i = 0; i < 2; i++) {
        int rr = i ? resp1 : resp0;
        #pragma unroll
        for (int j = 0; j < 8; j++) {
            float gg = acc[i][j] + RG[rr*512 + 256 + c0 + j];
            float cc = sC[(r0+i)*132 + c0 + j] * fast_tanh(gg);
            sC[(r0+i)*132 + c0 + j] = fast_tanh(cc);
        }
    }
    __syncthreads();
    loadW256(sW, W_ih + 384, 512, tid);     // o-gate cols
    __syncthreads();

    // stage 4: o gate -> h = sig(o)*tanh(c)
    gemm32(sIn, sW, acc, r0, c0);
    #pragma unroll
    for (int i = 0; i < 2; i++) {
        int rr = i ? resp1 : resp0;
        int grow = row0 + r0 + i;
        float hv[8];
        #pragma unroll
        for (int j = 0; j < 8; j++) {
            float go = acc[i][j] + RG[rr*512 + 384 + c0 + j];
            hv[j] = fast_sigmoid(go) * sC[(r0+i)*132 + c0 + j];
            sC[(r0+i)*132 + c0 + j] = hv[j];
        }
        *(float4*)(H + (size_t)grow*kD + c0)     = make_float4(hv[0],hv[1],hv[2],hv[3]);
        *(float4*)(H + (size_t)grow*kD + c0 + 4) = make_float4(hv[4],hv[5],hv[6],hv[7]);
    }
    __syncthreads();

    // a_state = h . qv + c_q  (8 threads/row, 16 dims each)
    {
        int lr = tid >> 3, part = tid & 7;
        int grow = row0 + lr;
        int b = grow / kS, s = grow % kS;
        float p = 0.f;
        #pragma unroll
        for (int d = 0; d < 16; d++)
            p += sC[lr*132 + part*16 + d] * sqv[part*16 + d];
        p += __shfl_down_sync(0xffffffffu, p, 4);
        p += __shfl_down_sync(0xffffffffu, p, 2);
        p += __shfl_down_sync(0xffffffffu, p, 1);
        if (part == 0 && s < kT)
            AS[b*kT + s] = p + vec[256];
    }
}

// ---------------- fused attention + prediction: one warp per (b,t) ----------------
__global__ __launch_bounds__(32, 24) void pred_kernel(
    const int* __restrict__ question,
    const int* __restrict__ qs_skills,
    const float* __restrict__ emb_q,
    const float* __restrict__ emb_s,
    float* __restrict__ out)
{
    const float* h   = g_buf + O_H;
    const float* as  = g_buf + O_AS;
    const float* vec = g_buf + O_V;

    __shared__ __align__(16) float sqs[5][kD];

    const int t = kT - 1 - blockIdx.x;     // big t first
    const int b = blockIdx.y;
    const int lane = threadIdx.x;

    int q = __ldg(&question[b*kS + t + 1]);
    ((float4*)sqs[0])[lane] = __ldg((const float4*)(emb_q + (size_t)q*kD) + lane);
    #pragma unroll
    for (int m = 1; m < 5; m++) {
        int si = __ldg(&qs_skills[q*4 + m - 1]);
        ((float4*)sqs[m])[lane] = __ldg((const float4*)(emb_s + (size_t)si*kD) + lane);
    }
    __syncwarp();

    // a_qs[m] = dot(sqs[m], kv); softmax over m (c_k cancels)
    float4 kv4 = *((const float4*)(vec + kD) + lane);
    float r[5];
    #pragma unroll
    for (int m = 0; m < 5; m++) {
        float4 s4 = ((float4*)sqs[m])[lane];
        float p = s4.x*kv4.x + s4.y*kv4.y + s4.z*kv4.z + s4.w*kv4.w;
        #pragma unroll
        for (int o = 16; o; o >>= 1) p += __shfl_xor_sync(0xffffffffu, p, o);
        r[m] = p;
    }
    {
        float mx = r[0];
        #pragma unroll
        for (int m = 1; m < 5; m++) mx = fmaxf(mx, r[m]);
        float se = 0.f;
        #pragma unroll
        for (int m = 0; m < 5; m++) { r[m] = __expf(r[m] - mx); se += r[m]; }
        float inv = __frcp_rn(se);
        #pragma unroll
        for (int m = 0; m < 5; m++) r[m] *= inv;
    }

    // max of a_state over n<=t
    float M1 = -1e30f;
    for (int n = lane; n <= t; n += 32) M1 = fmaxf(M1, as[b*kT + n]);
    #pragma unroll
    for (int o = 16; o; o >>= 1) M1 = fmaxf(M1, __shfl_xor_sync(0xffffffffu, M1, o));

    float sum_v = 0.f, sum_e = 0.f;
    for (int n = lane; n <= t; n += 32) {
        float e = __expf(as[b*kT + n] - M1);
        const float4* hr = (const float4*)(h + ((size_t)b*kS + n)*kD);
        float in0 = 0.f, in1 = 0.f, in2 = 0.f, in3 = 0.f, in4 = 0.f;
        #pragma unroll 8
        for (int d4 = 0; d4 < 32; d4++) {
            float4 hv = __ldg(&hr[d4]);
            int dd = d4 * 4;
            in0 += hv.x*sqs[0][dd] + hv.y*sqs[0][dd+1] + hv.z*sqs[0][dd+2] + hv.w*sqs[0][dd+3];
            in1 += hv.x*sqs[1][dd] + hv.y*sqs[1][dd+1] + hv.z*sqs[1][dd+2] + hv.w*sqs[1][dd+3];
            in2 += hv.x*sqs[2][dd] + hv.y*sqs[2][dd+1] + hv.z*sqs[2][dd+2] + hv.w*sqs[2][dd+3];
            in3 += hv.x*sqs[3][dd] + hv.y*sqs[3][dd+1] + hv.z*sqs[3][dd+2] + hv.w*sqs[3][dd+3];
            in4 += hv.x*sqs[4][dd] + hv.y*sqs[4][dd+1] + hv.z*sqs[4][dd+2] + hv.w*sqs[4][dd+3];
        }
        float sv = r[0]*fast_sigmoid(in0) + r[1]*fast_sigmoid(in1) + r[2]*fast_sigmoid(in2)
                 + r[3]*fast_sigmoid(in3) + r[4]*fast_sigmoid(in4);
        sum_v += e * sv;
        sum_e += e;
    }
    #pragma unroll
    for (int o = 16; o; o >>= 1) {
        sum_v += __shfl_xor_sync(0xffffffffu, sum_v, o);
        sum_e += __shfl_xor_sync(0xffffffffu, sum_e, o);
    }
    if (lane == 0) {
        out[b*kS + t + 1] = sum_v / sum_e;
        if (t == 0) out[b*kS] = 0.f;
    }
}

// ---------------- launch ----------------
extern "C" void kernel_launch(void* const* d_in, const int* in_sizes, int n_in,
                              void* d_out, int out_size)
{
    const int*   question = (const int*)  d_in[0];
    const int*   response = (const int*)  d_in[1];
    const int*   q_nbr    = (const int*)  d_in[3];
    const int*   s_nbr    = (const int*)  d_in[4];
    const int*   qs_sk    = (const int*)  d_in[5];
    const float* emb_q    = (const float*)d_in[6];
    const float* emb_s    = (const float*)d_in[7];
    const float* emb_r    = (const float*)d_in[8];
    const float* W_ih     = (const float*)d_in[9];
    const float* b_ih     = (const float*)d_in[10];
    const float* b_hh     = (const float*)d_in[11];
    const float* ft_W     = (const float*)d_in[12];
    const float* ft_b     = (const float*)d_in[13];
    const float* agg_W    = (const float*)d_in[14];
    const float* agg_b    = (const float*)d_in[15];
    const float* last_W   = (const float*)d_in[16];
    const float* last_b   = (const float*)d_in[17];
    const float* q_W      = (const float*)d_in[18];
    const float* q_b      = (const float*)d_in[19];
    const float* k_W      = (const float*)d_in[20];
    const float* k_b      = (const float*)d_in[21];
    const float* w_W      = (const float*)d_in[22];
    float* out = (float*)d_out;

    float* buf = nullptr;
    cudaGetSymbolAddress((void**)&buf, g_buf);
    float* TA0 = buf + O_TA0;
    float* TA1 = buf + O_TA1;
    float* TA2 = buf + O_TA2;
    float* TB0 = buf + O_TB0;
    float* TB1 = buf + O_TB1;

    const int HOP_SMEM  = (kD*kD   + 64*132) * (int)sizeof(float);
    const int HOP2_SMEM = (2*kD*kD + 64*132) * (int)sizeof(float);
    const int RC_SMEM   = (kD*kD + 2*32*132 + 128) * (int)sizeof(float);
    static bool attr_done = false;
    if (!attr_done) {
        cudaFuncSetAttribute(hop_kernel,      cudaFuncAttributeMaxDynamicSharedMemorySize, HOP_SMEM);
        cudaFuncSetAttribute(hop2_kernel,     cudaFuncAttributeMaxDynamicSharedMemorySize, HOP2_SMEM);
        cudaFuncSetAttribute(rowchain_kernel, cudaFuncAttributeMaxDynamicSharedMemorySize, RC_SMEM);
        attr_done = true;
    }

    const int gq = (kNQ + 63) / 64;        // 157
    const int gs = (kNS + 63) / 64;        // 8
    const float iq = 1.f/kQN, is = 1.f/kSN;

    PrepArgs noprep = {}; noprep.enable = 0;

    // level 0: TA0, TA2, TA1  (+ prep block)
    {
        HopParams p;
        p.nt = 3;
        p.t[0] = { emb_q, q_nbr, emb_s, agg_W,           agg_b,       TA0, kQN, iq, kNQ, 0 };
        p.t[1] = { emb_q, q_nbr, emb_s, agg_W + 2*16384, agg_b + 256, TA2, kQN, iq, kNQ, gq };
        p.t[2] = { emb_s, s_nbr, emb_q, agg_W + 16384,   agg_b + 128, TA1, kSN, is, kNS, 2*gq };
        p.prep = { q_W, q_b, k_W, k_b, w_W, emb_r, W_ih, b_ih, b_hh, 1 };
        hop_kernel<<<2*gq + gs + 1, 512, HOP_SMEM>>>(p);
    }
    // level 1: TB0, TB1
    {
        HopParams p;
        p.nt = 2;
        p.t[0] = { TA0, q_nbr, TA1, agg_W,         agg_b,       TB0, kQN, iq, kNQ, 0 };
        p.t[1] = { TA1, s_nbr, TA2, agg_W + 16384, agg_b + 128, TB1, kSN, is, kNS, gq };
        p.t[2] = p.t[1];
        p.prep = noprep;
        hop_kernel<<<gq + gs, 512, HOP_SMEM>>>(p);
    }
    // level 2 + last projection fused -> A
    hop2_kernel<<<gq, 512, HOP2_SMEM>>>(q_nbr, agg_W, agg_b, last_W, last_b);

    rowchain_kernel<<<(kB*kS)/32, 256, RC_SMEM>>>(question, response, ft_W, ft_b, W_ih);

    dim3 pg(kT, kB);
    pred_kernel<<<pg, 32>>>(question, qs_sk, emb_q, emb_s, out);
}

// round 7
// speedup vs baseline: 1.7691x; 1.0249x over previous
#include <cuda_runtime.h>
#include <math.h>
#include <stdint.h>

// ---------------- problem constants ----------------
#define kNQ 10000
#define kNS 500
#define kQN 4
#define kSN 10
#define kB  32
#define kS  200
#define kD  128
#define kT  199   // S-1

// ---------------- scratch layout (floats) ----------------
__host__ __device__ constexpr size_t O_TA0 = 0;
__host__ __device__ constexpr size_t O_TA1 = O_TA0 + (size_t)kNQ*kD;
__host__ __device__ constexpr size_t O_TA2 = O_TA1 + (size_t)kNS*kD;
__host__ __device__ constexpr size_t O_TB0 = O_TA2 + (size_t)kNQ*kD;
__host__ __device__ constexpr size_t O_TB1 = O_TB0 + (size_t)kNQ*kD;
__host__ __device__ constexpr size_t O_A   = O_TB1 + (size_t)kNS*kD;
__host__ __device__ constexpr size_t O_H   = O_A   + (size_t)kNQ*kD;
__host__ __device__ constexpr size_t O_AS  = O_H   + (size_t)kB*kS*kD;
__host__ __device__ constexpr size_t O_V   = O_AS  + (size_t)kB*kT;   // qv[128], kv[128], c_q, c_k
__host__ __device__ constexpr size_t O_RG  = O_V   + 258;             // r_gates 2x512
__host__ __device__ constexpr size_t G_TOTAL = O_RG + 1024;

__device__ float g_buf[G_TOTAL];

// ---------------- fast math ----------------
__device__ __forceinline__ float fast_tanh(float x) {
    float y;
    asm("tanh.approx.f32 %0, %1;" : "=f"(y) : "f"(x));
    return y;
}
__device__ __forceinline__ float fast_sigmoid(float x) {
    return 0.5f * fast_tanh(0.5f * x) + 0.5f;
}

// ---------------- task structs ----------------
struct HopTask {
    const float* base;
    const int*   nbrs;
    const float* tbl;
    const float* W;
    const float* bias;
    float*       out;
    int knbr; float invk;
    int R; int blk0;
};
struct PrepArgs {
    const float *qW, *qb, *kW, *kb, *wW, *embr, *Wih, *bih, *bhh;
    int enable;
};
struct HopParams { HopTask t[3]; int nt; PrepArgs prep; };

// ---------------- fused multi-task hop kernel (512 thr, 64 rows, 2x8 scalar) ----------------
__global__ __launch_bounds__(512, 2) void hop_kernel(const HopParams p)
{
    extern __shared__ float sm[];
    float* sW  = sm;                 // 128x128
    float* sIn = sm + kD*kD;         // 64x132
    const int tid = threadIdx.x;

    // prep block (independent side-work; consumers run 3 kernels later)
    if (p.prep.enable && blockIdx.x == (int)gridDim.x - 1) {
        const PrepArgs& A = p.prep;
        float* vec = g_buf + O_V;
        float* rg  = g_buf + O_RG;
        int t = tid;
        if (t < kD) {
            float sq = 0.f, sk = 0.f;
            #pragma unroll 4
            for (int j = 0; j < kD; j++) {
                sq += A.qW[t*kD + j] * A.wW[j];
                sk += A.kW[t*kD + j] * A.wW[kD + j];
            }
            vec[t]      = sq;
            vec[kD + t] = sk;
        }
        if (t == 256) {
            float s = 0.f;
            for (int j = 0; j < kD; j++) s += A.qb[j] * A.wW[j];
            vec[256] = s;
        }
        if (t == 257) {
            float s = 0.f;
            for (int j = 0; j < kD; j++) s += A.kb[j] * A.wW[kD + j];
            vec[257] = s;
        }
        {
            for (int r = 0; r < 2; r++) {
                float s = A.bih[t] + A.bhh[t];
                #pragma unroll 4
                for (int k = 0; k < kD; k++)
                    s += A.embr[r*kD + k] * A.Wih[(size_t)(kD + k)*512 + t];
                rg[r*512 + t] = s;
            }
        }
        return;
    }

    int ti = 0;
    #pragma unroll
    for (int i = 1; i < 3; i++)
        if (i < p.nt && (int)blockIdx.x >= p.t[i].blk0) ti = i;
    const HopTask& T = p.t[ti];
    const int row0 = (blockIdx.x - T.blk0) * 64;

    // load W (128x128): 4096 float4 / 512 thr
    {
        const float4* Wp = (const float4*)T.W;
        #pragma unroll
        for (int i = 0; i < 8; i++)
            ((float4*)sW)[tid + i*512] = __ldg(&Wp[tid + i*512]);
    }

    // build 64 input rows (8 threads/row, 16 dims = 4 float4 each)
    {
        int lr = tid >> 3, part = tid & 7;
        int gr = row0 + lr;
        float4 v[4];
        if (gr < T.R) {
            const float4* bp = (const float4*)(T.base + (size_t)gr*kD) + part*4;
            #pragma unroll
            for (int d = 0; d < 4; d++) v[d] = __ldg(&bp[d]);
            if (T.knbr > 0) {
                float4 s[4];
                #pragma unroll
                for (int d = 0; d < 4; d++) s[d] = make_float4(0.f,0.f,0.f,0.f);
                for (int j = 0; j < T.knbr; j++) {
                    int nb = __ldg(&T.nbrs[(size_t)gr*T.knbr + j]);
                    const float4* tp = (const float4*)(T.tbl + (size_t)nb*kD) + part*4;
                    #pragma unroll
                    for (int d = 0; d < 4; d++) {
                        float4 x = __ldg(&tp[d]);
                        s[d].x += x.x; s[d].y += x.y; s[d].z += x.z; s[d].w += x.w;
                    }
                }
                #pragma unroll
                for (int d = 0; d < 4; d++) {
                    v[d].x += s[d].x * T.invk; v[d].y += s[d].y * T.invk;
                    v[d].z += s[d].z * T.invk; v[d].w += s[d].w * T.invk;
                }
            }
        } else {
            #pragma unroll
            for (int d = 0; d < 4; d++) v[d] = make_float4(0.f,0.f,0.f,0.f);
        }
        #pragma unroll
        for (int d = 0; d < 4; d++)
            *(float4*)(sIn + lr*132 + part*16 + d*4) = v[d];
    }
    __syncthreads();

    // 64x128 GEMM: thread tile 2 rows x 8 cols (scalar)
    const int r0 = (tid >> 4) * 2;
    const int c0 = (tid & 15) * 8;
    float acc[2][8];
    #pragma unroll
    for (int i = 0; i < 2; i++)
        #pragma unroll
        for (int j = 0; j < 8; j++) acc[i][j] = 0.f;

    #pragma unroll 4
    for (int k = 0; k < kD; k++) {
        float a0 = sIn[(r0+0)*132 + k];
        float a1 = sIn[(r0+1)*132 + k];
        float4 b0 = *(const float4*)(sW + k*kD + c0);
        float4 b1 = *(const float4*)(sW + k*kD + c0 + 4);
        float bb[8] = {b0.x,b0.y,b0.z,b0.w,b1.x,b1.y,b1.z,b1.w};
        #pragma unroll
        for (int j = 0; j < 8; j++) {
            acc[0][j] += a0*bb[j];
            acc[1][j] += a1*bb[j];
        }
    }

    float bsv[8];
    #pragma unroll
    for (int j = 0; j < 8; j++) bsv[j] = __ldg(&T.bias[c0 + j]);

    #pragma unroll
    for (int i = 0; i < 2; i++) {
        int gr = row0 + r0 + i;
        if (gr >= T.R) continue;
        float4 o0, o1;
        o0.x = fast_tanh(acc[i][0] + bsv[0]); o0.y = fast_tanh(acc[i][1] + bsv[1]);
        o0.z = fast_tanh(acc[i][2] + bsv[2]); o0.w = fast_tanh(acc[i][3] + bsv[3]);
        o1.x = fast_tanh(acc[i][4] + bsv[4]); o1.y = fast_tanh(acc[i][5] + bsv[5]);
        o1.z = fast_tanh(acc[i][6] + bsv[6]); o1.w = fast_tanh(acc[i][7] + bsv[7]);
        *(float4*)(T.out + (size_t)gr*kD + c0)     = o0;
        *(float4*)(T.out + (size_t)gr*kD + c0 + 4) = o1;
    }
}

// ---------------- fused level2 + last projection (512 thr, 2x64 rows/block, grid 79) ----------------
__global__ __launch_bounds__(512, 1) void hop2_kernel(
    const int* __restrict__ q_nbr,
    const float* __restrict__ aggW, const float* __restrict__ aggb,
    const float* __restrict__ lastW, const float* __restrict__ lastb)
{
    extern __shared__ float sm[];
    float* sW1 = sm;                     // agg_W[0]
    float* sW2 = sm + kD*kD;             // last_W
    float* sIn = sm + 2*kD*kD;           // 64x132
    const int tid = threadIdx.x;

    const float* TB0 = g_buf + O_TB0;
    const float* TB1 = g_buf + O_TB1;
    float* A = g_buf + O_A;

    {
        const float4* W1p = (const float4*)aggW;
        const float4* W2p = (const float4*)lastW;
        #pragma unroll
        for (int i = 0; i < 8; i++) {
            ((float4*)sW1)[tid + i*512] = __ldg(&W1p[tid + i*512]);
            ((float4*)sW2)[tid + i*512] = __ldg(&W2p[tid + i*512]);
        }
    }

    const int r0 = (tid >> 4) * 2;
    const int c0 = (tid & 15) * 8;
    float ab[8], lb[8];
    #pragma unroll
    for (int j = 0; j < 8; j++) { ab[j] = __ldg(&aggb[c0+j]); lb[j] = __ldg(&lastb[c0+j]); }

    for (int half = 0; half < 2; half++) {
        const int row0 = (blockIdx.x * 2 + half) * 64;
        __syncthreads();   // previous iteration's reads of sIn done

        // gather: TB0[r] + mean_j TB1[q_nbr[r][j]]
        {
            int lr = tid >> 3, part = tid & 7;
            int gr = row0 + lr;
            float4 v[4];
            if (gr < kNQ) {
                const float4* bp = (const float4*)(TB0 + (size_t)gr*kD) + part*4;
                #pragma unroll
                for (int d = 0; d < 4; d++) v[d] = bp[d];
                float4 s[4];
                #pragma unroll
                for (int d = 0; d < 4; d++) s[d] = make_float4(0.f,0.f,0.f,0.f);
                #pragma unroll
                for (int j = 0; j < kQN; j++) {
                    int nb = __ldg(&q_nbr[(size_t)gr*kQN + j]);
                    const float4* tp = (const float4*)(TB1 + (size_t)nb*kD) + part*4;
                    #pragma unroll
                    for (int d = 0; d < 4; d++) {
                        float4 x = tp[d];
                        s[d].x += x.x; s[d].y += x.y; s[d].z += x.z; s[d].w += x.w;
                    }
                }
                const float iq = 1.f/kQN;
                #pragma unroll
                for (int d = 0; d < 4; d++) {
                    v[d].x += s[d].x*iq; v[d].y += s[d].y*iq;
                    v[d].z += s[d].z*iq; v[d].w += s[d].w*iq;
                }
            } else {
                #pragma unroll
                for (int d = 0; d < 4; d++) v[d] = make_float4(0.f,0.f,0.f,0.f);
            }
            #pragma unroll
            for (int d = 0; d < 4; d++)
                *(float4*)(sIn + lr*132 + part*16 + d*4) = v[d];
        }
        __syncthreads();

        float acc[2][8];

        // GEMM 1: tanh(x @ agg_W0 + agg_b0)
        #pragma unroll
        for (int i = 0; i < 2; i++)
            #pragma unroll
            for (int j = 0; j < 8; j++) acc[i][j] = 0.f;
        #pragma unroll 4
        for (int k = 0; k < kD; k++) {
            float a0 = sIn[(r0+0)*132 + k];
            float a1 = sIn[(r0+1)*132 + k];
            float4 b0 = *(const float4*)(sW1 + k*kD + c0);
            float4 b1 = *(const float4*)(sW1 + k*kD + c0 + 4);
            float bb[8] = {b0.x,b0.y,b0.z,b0.w,b1.x,b1.y,b1.z,b1.w};
            #pragma unroll
            for (int j = 0; j < 8; j++) {
                acc[0][j] += a0*bb[j];
                acc[1][j] += a1*bb[j];
            }
        }
        __syncthreads();
        #pragma unroll
        for (int i = 0; i < 2; i++)
            #pragma unroll
            for (int j = 0; j < 8; j++)
                sIn[(r0+i)*132 + c0 + j] = fast_tanh(acc[i][j] + ab[j]);
        __syncthreads();

        // GEMM 2: tanh(y @ last_W + last_b) -> A
        #pragma unroll
        for (int i = 0; i < 2; i++)
            #pragma unroll
            for (int j = 0; j < 8; j++) acc[i][j] = 0.f;
        #pragma unroll 4
        for (int k = 0; k < kD; k++) {
            float a0 = sIn[(r0+0)*132 + k];
            float a1 = sIn[(r0+1)*132 + k];
            float4 b0 = *(const float4*)(sW2 + k*kD + c0);
            float4 b1 = *(const float4*)(sW2 + k*kD + c0 + 4);
            float bb[8] = {b0.x,b0.y,b0.z,b0.w,b1.x,b1.y,b1.z,b1.w};
            #pragma unroll
            for (int j = 0; j < 8; j++) {
                acc[0][j] += a0*bb[j];
                acc[1][j] += a1*bb[j];
            }
        }
        #pragma unroll
        for (int i = 0; i < 2; i++) {
            int gr = row0 + r0 + i;
            if (gr >= kNQ) continue;
            float4 o0, o1;
            o0.x = fast_tanh(acc[i][0] + lb[0]); o0.y = fast_tanh(acc[i][1] + lb[1]);
            o0.z = fast_tanh(acc[i][2] + lb[2]); o0.w = fast_tanh(acc[i][3] + lb[3]);
            o1.x = fast_tanh(acc[i][4] + lb[4]); o1.y = fast_tanh(acc[i][5] + lb[5]);
            o1.z = fast_tanh(acc[i][6] + lb[6]); o1.w = fast_tanh(acc[i][7] + lb[7]);
            *(float4*)(A + (size_t)gr*kD + c0)     = o0;
            *(float4*)(A + (size_t)gr*kD + c0 + 4) = o1;
        }
    }
}

// ---------------- rowchain, wide-gates: QT GEMM then ONE 64x384 gates GEMM ----------------
// 512 thr, 64 rows/block, grid 100. smem: 3x(128x128) W + 64x132 input + qv.
__global__ __launch_bounds__(512, 1) void rowchain_kernel(
    const int* __restrict__ question, const int* __restrict__ response,
    const float* __restrict__ ft_W, const float* __restrict__ ft_b,
    const float* __restrict__ W_ih)
{
    extern __shared__ float sm[];
    float* sW  = sm;                   // up to 3x 128x128
    float* sIn = sm + 3*kD*kD;         // 64x132
    float* sqv = sIn + 64*132;         // 128

    const float* A   = g_buf + O_A;
    const float* vec = g_buf + O_V;
    const float* RG  = g_buf + O_RG;
    float* H  = g_buf + O_H;
    float* AS = g_buf + O_AS;

    const int tid = threadIdx.x;
    const int row0 = blockIdx.x * 64;
    if (tid < kD) sqv[tid] = vec[tid];

    // gather A[question[row]] (8 threads/row, 16 dims = 4 float4)
    {
        int lr = tid >> 3, part = tid & 7;
        int grow = row0 + lr;
        int q = __ldg(&question[grow]);
        const float4* ap = (const float4*)(A + (size_t)q*kD) + part*4;
        #pragma unroll
        for (int d = 0; d < 4; d++)
            *(float4*)(sIn + lr*132 + part*16 + d*4) = ap[d];
    }
    // load ft_W into sW[0:16384]
    {
        const float4* Wp = (const float4*)ft_W;
        #pragma unroll
        for (int i = 0; i < 8; i++)
            ((float4*)sW)[tid + i*512] = __ldg(&Wp[tid + i*512]);
    }
    __syncthreads();

    const int r0 = (tid >> 4) * 2;     // 0..62
    const int c0 = (tid & 15) * 8;     // 0..120

    // stage 1: QT = relu(in @ ft_W + ft_b)
    float acc[2][8];
    #pragma unroll
    for (int i = 0; i < 2; i++)
        #pragma unroll
        for (int j = 0; j < 8; j++) acc[i][j] = 0.f;
    #pragma unroll 4
    for (int k = 0; k < kD; k++) {
        float a0 = sIn[(r0+0)*132 + k];
        float a1 = sIn[(r0+1)*132 + k];
        float4 b0 = *(const float4*)(sW + k*kD + c0);
        float4 b1 = *(const float4*)(sW + k*kD + c0 + 4);
        float bb[8] = {b0.x,b0.y,b0.z,b0.w,b1.x,b1.y,b1.z,b1.w};
        #pragma unroll
        for (int j = 0; j < 8; j++) {
            acc[0][j] += a0*bb[j];
            acc[1][j] += a1*bb[j];
        }
    }
    float fb[8];
    #pragma unroll
    for (int j = 0; j < 8; j++) fb[j] = __ldg(&ft_b[c0 + j]);
    __syncthreads();                   // all GEMM reads of sIn/sW done
    #pragma unroll
    for (int i = 0; i < 2; i++)
        #pragma unroll
        for (int j = 0; j < 8; j++)
            sIn[(r0+i)*132 + c0 + j] = fmaxf(acc[i][j] + fb[j], 0.f);

    // load gate W slices: i=[0:128), g=[256:384), o=[384:512) of W_ih (128x512)
    {
        const int gofs[3] = {0, 256, 384};
        #pragma unroll
        for (int g = 0; g < 3; g++) {
            const float* Wg = W_ih + gofs[g];
            #pragma unroll
            for (int ii = 0; ii < 8; ii++) {
                int i = tid + ii*512;            // 0..4095
                int k = i >> 5, c4 = i & 31;
                ((float4*)(sW + g*16384 + k*kD))[c4] =
                    __ldg((const float4*)(Wg + (size_t)k*512) + c4);
            }
        }
    }
    __syncthreads();

    // stage 2: all three gates in one pass. Thread tile: 2 rows x (3 gates x 8 cols).
    float ai[2][8], ag[2][8], ao[2][8];
    #pragma unroll
    for (int i = 0; i < 2; i++)
        #pragma unroll
        for (int j = 0; j < 8; j++) { ai[i][j]=0.f; ag[i][j]=0.f; ao[i][j]=0.f; }

    #pragma unroll 2
    for (int k = 0; k < kD; k++) {
        float a0 = sIn[(r0+0)*132 + k];
        float a1 = sIn[(r0+1)*132 + k];
        float4 i0 = *(const float4*)(sW + 0*16384 + k*kD + c0);
        float4 i1 = *(const float4*)(sW + 0*16384 + k*kD + c0 + 4);
        float4 g0 = *(const float4*)(sW + 1*16384 + k*kD + c0);
        float4 g1 = *(const float4*)(sW + 1*16384 + k*kD + c0 + 4);
        float4 o0 = *(const float4*)(sW + 2*16384 + k*kD + c0);
        float4 o1 = *(const float4*)(sW + 2*16384 + k*kD + c0 + 4);
        float ib[8] = {i0.x,i0.y,i0.z,i0.w,i1.x,i1.y,i1.z,i1.w};
        float gb[8] = {g0.x,g0.y,g0.z,g0.w,g1.x,g1.y,g1.z,g1.w};
        float ob[8] = {o0.x,o0.y,o0.z,o0.w,o1.x,o1.y,o1.z,o1.w};
        #pragma unroll
        for (int j = 0; j < 8; j++) {
            ai[0][j] += a0*ib[j]; ai[1][j] += a1*ib[j];
            ag[0][j] += a0*gb[j]; ag[1][j] += a1*gb[j];
            ao[0][j] += a0*ob[j]; ao[1][j] += a1*ob[j];
        }
    }

    // epilogue: gates -> h (registers), write H, partial a_state
    const float cq = vec[256];
    #pragma unroll
    for (int i = 0; i < 2; i++) {
        int grow = row0 + r0 + i;
        int rr = __ldg(&response[grow]);
        const float* rgi = RG + rr*512 + 0   + c0;
        const float* rgg = RG + rr*512 + 256 + c0;
        const float* rgo = RG + rr*512 + 384 + c0;
        float hv[8];
        float p = 0.f;
        #pragma unroll
        for (int j = 0; j < 8; j++) {
            float iv = fast_sigmoid(ai[i][j] + rgi[j]);
            float gv = fast_tanh   (ag[i][j] + rgg[j]);
            float ov = fast_sigmoid(ao[i][j] + rgo[j]);
            float cc = iv * gv;
            hv[j] = ov * fast_tanh(cc);
            p += hv[j] * sqv[c0 + j];
        }
        *(float4*)(H + (size_t)grow*kD + c0)     = make_float4(hv[0],hv[1],hv[2],hv[3]);
        *(float4*)(H + (size_t)grow*kD + c0 + 4) = make_float4(hv[4],hv[5],hv[6],hv[7]);
        // reduce p over the 16 threads sharing this row (lanes tid&15, width 16)
        p += __shfl_down_sync(0xffffffffu, p, 8, 16);
        p += __shfl_down_sync(0xffffffffu, p, 4, 16);
        p += __shfl_down_sync(0xffffffffu, p, 2, 16);
        p += __shfl_down_sync(0xffffffffu, p, 1, 16);
        if ((tid & 15) == 0) {
            int b = grow / kS, s = grow % kS;
            if (s < kT) AS[b*kT + s] = p + cq;
        }
    }
}

// ---------------- fused attention + prediction: one warp per (b,t) ----------------
__global__ __launch_bounds__(32, 24) void pred_kernel(
    const int* __restrict__ question,
    const int* __restrict__ qs_skills,
    const float* __restrict__ emb_q,
    const float* __restrict__ emb_s,
    float* __restrict__ out)
{
    const float* h   = g_buf + O_H;
    const float* as  = g_buf + O_AS;
    const float* vec = g_buf + O_V;

    __shared__ __align__(16) float sqs[5][kD];

    const int t = kT - 1 - blockIdx.x;     // big t first
    const int b = blockIdx.y;
    const int lane = threadIdx.x;

    int q = __ldg(&question[b*kS + t + 1]);
    ((float4*)sqs[0])[lane] = __ldg((const float4*)(emb_q + (size_t)q*kD) + lane);
    #pragma unroll
    for (int m = 1; m < 5; m++) {
        int si = __ldg(&qs_skills[q*4 + m - 1]);
        ((float4*)sqs[m])[lane] = __ldg((const float4*)(emb_s + (size_t)si*kD) + lane);
    }
    __syncwarp();

    // a_qs[m] = dot(sqs[m], kv); softmax over m (c_k cancels)
    float4 kv4 = *((const float4*)(vec + kD) + lane);
    float r[5];
    #pragma unroll
    for (int m = 0; m < 5; m++) {
        float4 s4 = ((float4*)sqs[m])[lane];
        float p = s4.x*kv4.x + s4.y*kv4.y + s4.z*kv4.z + s4.w*kv4.w;
        #pragma unroll
        for (int o = 16; o; o >>= 1) p += __shfl_xor_sync(0xffffffffu, p, o);
        r[m] = p;
    }
    {
        float mx = r[0];
        #pragma unroll
        for (int m = 1; m < 5; m++) mx = fmaxf(mx, r[m]);
        float se = 0.f;
        #pragma unroll
        for (int m = 0; m < 5; m++) { r[m] = __expf(r[m] - mx); se += r[m]; }
        float inv = __frcp_rn(se);
        #pragma unroll
        for (int m = 0; m < 5; m++) r[m] *= inv;
    }

    // max of a_state over n<=t
    float M1 = -1e30f;
    for (int n = lane; n <= t; n += 32) M1 = fmaxf(M1, as[b*kT + n]);
    #pragma unroll
    for (int o = 16; o; o >>= 1) M1 = fmaxf(M1, __shfl_xor_sync(0xffffffffu, M1, o));

    float sum_v = 0.f, sum_e = 0.f;
    for (int n = lane; n <= t; n += 32) {
        float e = __expf(as[b*kT + n] - M1);
        const float4* hr = (const float4*)(h + ((size_t)b*kS + n)*kD);
        float in0 = 0.f, in1 = 0.f, in2 = 0.f, in3 = 0.f, in4 = 0.f;
        #pragma unroll 8
        for (int d4 = 0; d4 < 32; d4++) {
            float4 hv = __ldg(&hr[d4]);
            int dd = d4 * 4;
            in0 += hv.x*sqs[0][dd] + hv.y*sqs[0][dd+1] + hv.z*sqs[0][dd+2] + hv.w*sqs[0][dd+3];
            in1 += hv.x*sqs[1][dd] + hv.y*sqs[1][dd+1] + hv.z*sqs[1][dd+2] + hv.w*sqs[1][dd+3];
            in2 += hv.x*sqs[2][dd] + hv.y*sqs[2][dd+1] + hv.z*sqs[2][dd+2] + hv.w*sqs[2][dd+3];
            in3 += hv.x*sqs[3][dd] + hv.y*sqs[3][dd+1] + hv.z*sqs[3][dd+2] + hv.w*sqs[3][dd+3];
            in4 += hv.x*sqs[4][dd] + hv.y*sqs[4][dd+1] + hv.z*sqs[4][dd+2] + hv.w*sqs[4][dd+3];
        }
        float sv = r[0]*fast_sigmoid(in0) + r[1]*fast_sigmoid(in1) + r[2]*fast_sigmoid(in2)
                 + r[3]*fast_sigmoid(in3) + r[4]*fast_sigmoid(in4);
        sum_v += e * sv;
        sum_e += e;
    }
    #pragma unroll
    for (int o = 16; o; o >>= 1) {
        sum_v += __shfl_xor_sync(0xffffffffu, sum_v, o);
        sum_e += __shfl_xor_sync(0xffffffffu, sum_e, o);
    }
    if (lane == 0) {
        out[b*kS + t + 1] = sum_v / sum_e;
        if (t == 0) out[b*kS] = 0.f;
    }
}

// ---------------- launch ----------------
extern "C" void kernel_launch(void* const* d_in, const int* in_sizes, int n_in,
                              void* d_out, int out_size)
{
    const int*   question = (const int*)  d_in[0];
    const int*   response = (const int*)  d_in[1];
    const int*   q_nbr    = (const int*)  d_in[3];
    const int*   s_nbr    = (const int*)  d_in[4];
    const int*   qs_sk    = (const int*)  d_in[5];
    const float* emb_q    = (const float*)d_in[6];
    const float* emb_s    = (const float*)d_in[7];
    const float* emb_r    = (const float*)d_in[8];
    const float* W_ih     = (const float*)d_in[9];
    const float* b_ih     = (const float*)d_in[10];
    const float* b_hh     = (const float*)d_in[11];
    const float* ft_W     = (const float*)d_in[12];
    const float* ft_b     = (const float*)d_in[13];
    const float* agg_W    = (const float*)d_in[14];
    const float* agg_b    = (const float*)d_in[15];
    const float* last_W   = (const float*)d_in[16];
    const float* last_b   = (const float*)d_in[17];
    const float* q_W      = (const float*)d_in[18];
    const float* q_b      = (const float*)d_in[19];
    const float* k_W      = (const float*)d_in[20];
    const float* k_b      = (const float*)d_in[21];
    const float* w_W      = (const float*)d_in[22];
    float* out = (float*)d_out;

    float* buf = nullptr;
    cudaGetSymbolAddress((void**)&buf, g_buf);
    float* TA0 = buf + O_TA0;
    float* TA1 = buf + O_TA1;
    float* TA2 = buf + O_TA2;
    float* TB0 = buf + O_TB0;
    float* TB1 = buf + O_TB1;

    const int HOP_SMEM  = (kD*kD   + 64*132) * (int)sizeof(float);
    const int HOP2_SMEM = (2*kD*kD + 64*132) * (int)sizeof(float);
    const int RC_SMEM   = (3*kD*kD + 64*132 + 128) * (int)sizeof(float);
    static bool attr_done = false;
    if (!attr_done) {
        cudaFuncSetAttribute(hop_kernel,      cudaFuncAttributeMaxDynamicSharedMemorySize, HOP_SMEM);
        cudaFuncSetAttribute(hop2_kernel,     cudaFuncAttributeMaxDynamicSharedMemorySize, HOP2_SMEM);
        cudaFuncSetAttribute(rowchain_kernel, cudaFuncAttributeMaxDynamicSharedMemorySize, RC_SMEM);
        attr_done = true;
    }

    const int gq = (kNQ + 63) / 64;        // 157
    const int gs = (kNS + 63) / 64;        // 8
    const float iq = 1.f/kQN, is = 1.f/kSN;

    PrepArgs noprep = {}; noprep.enable = 0;

    // level 0: TA0, TA2, TA1  (+ prep block)
    {
        HopParams p;
        p.nt = 3;
        p.t[0] = { emb_q, q_nbr, emb_s, agg_W,           agg_b,       TA0, kQN, iq, kNQ, 0 };
        p.t[1] = { emb_q, q_nbr, emb_s, agg_W + 2*16384, agg_b + 256, TA2, kQN, iq, kNQ, gq };
        p.t[2] = { emb_s, s_nbr, emb_q, agg_W + 16384,   agg_b + 128, TA1, kSN, is, kNS, 2*gq };
        p.prep = { q_W, q_b, k_W, k_b, w_W, emb_r, W_ih, b_ih, b_hh, 1 };
        hop_kernel<<<2*gq + gs + 1, 512, HOP_SMEM>>>(p);
    }
    // level 1: TB0, TB1
    {
        HopParams p;
        p.nt = 2;
        p.t[0] = { TA0, q_nbr, TA1, agg_W,         agg_b,       TB0, kQN, iq, kNQ, 0 };
        p.t[1] = { TA1, s_nbr, TA2, agg_W + 16384, agg_b + 128, TB1, kSN, is, kNS, gq };
        p.t[2] = p.t[1];
        p.prep = noprep;
        hop_kernel<<<gq + gs, 512, HOP_SMEM>>>(p);
    }
    // level 2 + last projection fused -> A (grid 79, 2 halves/block: one clean wave)
    hop2_kernel<<<(kNQ + 127)/128, 512, HOP2_SMEM>>>(q_nbr, agg_W, agg_b, last_W, last_b);

    // row chain: wide gates (grid 100, 512 thr, 226 KB smem)
    rowchain_kernel<<<(kB*kS)/64, 512, RC_SMEM>>>(question, response, ft_W, ft_b, W_ih);

    dim3 pg(kT, kB);
    pred_kernel<<<pg, 32>>>(question, qs_sk, emb_q, emb_s, out);
}